// round 1
// baseline (speedup 1.0000x reference)
#include <cuda_runtime.h>
#include <cuda_bf16.h>

// Sinkhorn OT loss, B=1024, N=M=256, 100 iterations, eps=0.1.
// Strategy: one persistent CTA per batch. K = exp(-C/eps) held in shared
// memory as bf16 (row-padded to 258 elements -> conflict-free for BOTH
// row-access (K v) and column-access (K^T u) with 32-bit loads).
// fp32 accumulation throughout. Deterministic reduction via __device__ scratch.

#define B_TOT   1024
#define NN      256
#define MM      256
#define ITERS   100
#define INV_EPS 10.0f
#define EPS_DIV 1e-8f

#define ROWW 258                      // bf16 elems per padded row (129 words)
#define SMEM_BYTES (NN*ROWW*2 /*K*/ + 4*256*4 /*u,v,a,b*/ + 512*4 /*psum*/)

__device__ float g_cost[B_TOT];

__device__ __forceinline__ float bflo(unsigned int p) { return __uint_as_float(p << 16); }
__device__ __forceinline__ float bfhi(unsigned int p) { return __uint_as_float(p & 0xffff0000u); }

extern __shared__ unsigned char smem_raw[];

__global__ __launch_bounds__(256, 1)
void sinkhorn_kernel(const float* __restrict__ C,
                     const float* __restrict__ mass_pred,
                     const float* __restrict__ mass_target)
{
    unsigned short* sK = (unsigned short*)smem_raw;           // 256 x 258 bf16
    float* s_u  = (float*)(smem_raw + NN * ROWW * 2);         // 256
    float* s_v  = s_u + 256;                                  // 256
    float* s_a  = s_v + 256;                                  // 256
    float* s_b  = s_a + 256;                                  // 256
    float* s_ps = s_b + 256;                                  // 512 partials

    const int b = blockIdx.x;
    const int t = threadIdx.x;
    const float* __restrict__ Cb = C + (size_t)b * (NN * MM);
    const unsigned int* sKw = (const unsigned int*)sK;

    // ---------- Build K = exp(-C/eps) into smem (bf16, padded rows) ----------
    #pragma unroll 4
    for (int k = 0; k < 64; k++) {
        int idx4 = k * 256 + t;                 // coalesced float4 index
        float4 c = ((const float4*)Cb)[idx4];
        int lin = idx4 * 4;
        int n = lin >> 8;
        int m = lin & 255;
        __nv_bfloat162 p0 = __floats2bfloat162_rn(__expf(-c.x * INV_EPS),
                                                  __expf(-c.y * INV_EPS));
        __nv_bfloat162 p1 = __floats2bfloat162_rn(__expf(-c.z * INV_EPS),
                                                  __expf(-c.w * INV_EPS));
        *(__nv_bfloat162*)&sK[n * ROWW + m]     = p0;
        *(__nv_bfloat162*)&sK[n * ROWW + m + 2] = p1;
    }

    // ---------- Normalize masses: a = mp/sum(mp), b = mt/sum(mt) ----------
    float mpv = mass_pred[b * NN + t];
    float mtv = mass_target[b * MM + t];
    float sa = mpv, sb = mtv;
    #pragma unroll
    for (int o = 16; o; o >>= 1) {
        sa += __shfl_xor_sync(0xffffffffu, sa, o);
        sb += __shfl_xor_sync(0xffffffffu, sb, o);
    }
    if ((t & 31) == 0) { s_ps[t >> 5] = sa; s_ps[8 + (t >> 5)] = sb; }
    __syncthreads();
    float suma = 0.f, sumb = 0.f;
    #pragma unroll
    for (int w = 0; w < 8; w++) { suma += s_ps[w]; sumb += s_ps[8 + w]; }
    s_a[t] = mpv / (suma + EPS_DIV);
    s_b[t] = mtv / (sumb + EPS_DIV);
    s_u[t] = 1.0f;
    __syncthreads();

    // ---------- 100 Sinkhorn iterations ----------
    const int j  = t & 127;    // column-pair index: owns columns (2j, 2j+1)
    const int h  = t >> 7;     // n-half: rows [128h, 128h+128)
    const int n0 = h << 7;

    for (int it = 0; it < ITERS; it++) {
        // step 1: Kt_u[m] = sum_n K[n][m] * u[n]   (column access, split over h)
        float a0 = 0.f, a1 = 0.f;
        #pragma unroll 8
        for (int nn = 0; nn < 128; nn += 4) {
            float4 uu = *(const float4*)&s_u[n0 + nn];
            unsigned int p0 = sKw[(n0 + nn)     * 129 + j];
            unsigned int p1 = sKw[(n0 + nn + 1) * 129 + j];
            unsigned int p2 = sKw[(n0 + nn + 2) * 129 + j];
            unsigned int p3 = sKw[(n0 + nn + 3) * 129 + j];
            a0 += bflo(p0) * uu.x; a1 += bfhi(p0) * uu.x;
            a0 += bflo(p1) * uu.y; a1 += bfhi(p1) * uu.y;
            a0 += bflo(p2) * uu.z; a1 += bfhi(p2) * uu.z;
            a0 += bflo(p3) * uu.w; a1 += bfhi(p3) * uu.w;
        }
        *(float2*)&s_ps[(h << 8) + (j << 1)] = make_float2(a0, a1);
        __syncthreads();

        float kt = s_ps[t] + s_ps[256 + t];
        s_v[t] = __fdividef(s_b[t], kt + EPS_DIV);
        __syncthreads();

        // step 2: K_v[n] = sum_m K[n][m] * v[m]    (row access)
        float acc = 0.f;
        #pragma unroll 8
        for (int m = 0; m < 256; m += 4) {
            float4 vv = *(const float4*)&s_v[m];
            unsigned int q0 = sKw[t * 129 + (m >> 1)];
            unsigned int q1 = sKw[t * 129 + (m >> 1) + 1];
            acc += bflo(q0) * vv.x + bfhi(q0) * vv.y
                 + bflo(q1) * vv.z + bfhi(q1) * vv.w;
        }
        s_u[t] = __fdividef(s_a[t], acc + EPS_DIV);
        __syncthreads();
    }

    // ---------- ot_cost[b] = sum_{n,m} u[n] * K[n,m] * v[m] * C[n,m] ----------
    float acc = 0.f;
    #pragma unroll 4
    for (int k = 0; k < 64; k++) {
        int idx4 = k * 256 + t;
        float4 c = ((const float4*)Cb)[idx4];
        int lin = idx4 * 4;
        int n = lin >> 8;
        int m = lin & 255;
        float un = s_u[n];
        float4 vv = *(const float4*)&s_v[m];
        unsigned int q0 = sKw[n * 129 + (m >> 1)];
        unsigned int q1 = sKw[n * 129 + (m >> 1) + 1];
        acc += un * (bflo(q0) * vv.x * c.x + bfhi(q0) * vv.y * c.y
                   + bflo(q1) * vv.z * c.z + bfhi(q1) * vv.w * c.w);
    }
    #pragma unroll
    for (int o = 16; o; o >>= 1) acc += __shfl_xor_sync(0xffffffffu, acc, o);
    __syncthreads();              // s_ps reuse safe after this
    if ((t & 31) == 0) s_ps[t >> 5] = acc;
    __syncthreads();
    if (t == 0) {
        float s = 0.f;
        #pragma unroll
        for (int w = 0; w < 8; w++) s += s_ps[w];
        g_cost[b] = s;
    }
}

__global__ void reduce_kernel(float* __restrict__ out)
{
    __shared__ float sm[8];
    int t = threadIdx.x;
    float s = 0.f;
    #pragma unroll
    for (int i = t; i < B_TOT; i += 256) s += g_cost[i];
    #pragma unroll
    for (int o = 16; o; o >>= 1) s += __shfl_xor_sync(0xffffffffu, s, o);
    if ((t & 31) == 0) sm[t >> 5] = s;
    __syncthreads();
    if (t == 0) {
        float tot = 0.f;
        #pragma unroll
        for (int w = 0; w < 8; w++) tot += sm[w];
        out[0] = tot * (1.0f / B_TOT);
    }
}

extern "C" void kernel_launch(void* const* d_in, const int* in_sizes, int n_in,
                              void* d_out, int out_size)
{
    const float* C  = (const float*)d_in[0];
    const float* mp = (const float*)d_in[1];
    const float* mt = (const float*)d_in[2];
    float* out = (float*)d_out;

    cudaFuncSetAttribute(sinkhorn_kernel,
                         cudaFuncAttributeMaxDynamicSharedMemorySize, SMEM_BYTES);

    sinkhorn_kernel<<<B_TOT, 256, SMEM_BYTES>>>(C, mp, mt);
    reduce_kernel<<<1, 256>>>(out);
}

// round 2
// speedup vs baseline: 1.0025x; 1.0025x over previous
#include <cuda_runtime.h>
#include <cuda_bf16.h>

// Sinkhorn OT loss, B=1024, N=M=256, 100 iterations, eps=0.1.
// Strategy: one persistent CTA per batch. K = exp(-C/eps) held in shared
// memory as bf16 (row-padded to 258 elements -> conflict-free for BOTH
// row-access (K v) and column-access (K^T u) with 32-bit loads).
// fp32 accumulation throughout. Deterministic reduction via __device__ scratch.

#define B_TOT   1024
#define NN      256
#define MM      256
#define ITERS   100
#define INV_EPS 10.0f
#define EPS_DIV 1e-8f

#define ROWW 258                      // bf16 elems per padded row (129 words)
#define SMEM_BYTES (NN*ROWW*2 /*K*/ + 4*256*4 /*u,v,a,b*/ + 512*4 /*psum*/)

__device__ float g_cost[B_TOT];

__device__ __forceinline__ float bflo(unsigned int p) { return __uint_as_float(p << 16); }
__device__ __forceinline__ float bfhi(unsigned int p) { return __uint_as_float(p & 0xffff0000u); }

extern __shared__ unsigned char smem_raw[];

__global__ __launch_bounds__(256, 1)
void sinkhorn_kernel(const float* __restrict__ C,
                     const float* __restrict__ mass_pred,
                     const float* __restrict__ mass_target)
{
    unsigned short* sK = (unsigned short*)smem_raw;           // 256 x 258 bf16
    float* s_u  = (float*)(smem_raw + NN * ROWW * 2);         // 256
    float* s_v  = s_u + 256;                                  // 256
    float* s_a  = s_v + 256;                                  // 256
    float* s_b  = s_a + 256;                                  // 256
    float* s_ps = s_b + 256;                                  // 512 partials

    const int b = blockIdx.x;
    const int t = threadIdx.x;
    const float* __restrict__ Cb = C + (size_t)b * (NN * MM);
    const unsigned int* sKw = (const unsigned int*)sK;

    // ---------- Build K = exp(-C/eps) into smem (bf16, padded rows) ----------
    #pragma unroll 4
    for (int k = 0; k < 64; k++) {
        int idx4 = k * 256 + t;                 // coalesced float4 index
        float4 c = ((const float4*)Cb)[idx4];
        int lin = idx4 * 4;
        int n = lin >> 8;
        int m = lin & 255;
        __nv_bfloat162 p0 = __floats2bfloat162_rn(__expf(-c.x * INV_EPS),
                                                  __expf(-c.y * INV_EPS));
        __nv_bfloat162 p1 = __floats2bfloat162_rn(__expf(-c.z * INV_EPS),
                                                  __expf(-c.w * INV_EPS));
        *(__nv_bfloat162*)&sK[n * ROWW + m]     = p0;
        *(__nv_bfloat162*)&sK[n * ROWW + m + 2] = p1;
    }

    // ---------- Normalize masses: a = mp/sum(mp), b = mt/sum(mt) ----------
    float mpv = mass_pred[b * NN + t];
    float mtv = mass_target[b * MM + t];
    float sa = mpv, sb = mtv;
    #pragma unroll
    for (int o = 16; o; o >>= 1) {
        sa += __shfl_xor_sync(0xffffffffu, sa, o);
        sb += __shfl_xor_sync(0xffffffffu, sb, o);
    }
    if ((t & 31) == 0) { s_ps[t >> 5] = sa; s_ps[8 + (t >> 5)] = sb; }
    __syncthreads();
    float suma = 0.f, sumb = 0.f;
    #pragma unroll
    for (int w = 0; w < 8; w++) { suma += s_ps[w]; sumb += s_ps[8 + w]; }
    s_a[t] = mpv / (suma + EPS_DIV);
    s_b[t] = mtv / (sumb + EPS_DIV);
    s_u[t] = 1.0f;
    __syncthreads();

    // ---------- 100 Sinkhorn iterations ----------
    const int j  = t & 127;    // column-pair index: owns columns (2j, 2j+1)
    const int h  = t >> 7;     // n-half: rows [128h, 128h+128)
    const int n0 = h << 7;

    for (int it = 0; it < ITERS; it++) {
        // step 1: Kt_u[m] = sum_n K[n][m] * u[n]   (column access, split over h)
        float a0 = 0.f, a1 = 0.f;
        #pragma unroll 8
        for (int nn = 0; nn < 128; nn += 4) {
            float4 uu = *(const float4*)&s_u[n0 + nn];
            unsigned int p0 = sKw[(n0 + nn)     * 129 + j];
            unsigned int p1 = sKw[(n0 + nn + 1) * 129 + j];
            unsigned int p2 = sKw[(n0 + nn + 2) * 129 + j];
            unsigned int p3 = sKw[(n0 + nn + 3) * 129 + j];
            a0 += bflo(p0) * uu.x; a1 += bfhi(p0) * uu.x;
            a0 += bflo(p1) * uu.y; a1 += bfhi(p1) * uu.y;
            a0 += bflo(p2) * uu.z; a1 += bfhi(p2) * uu.z;
            a0 += bflo(p3) * uu.w; a1 += bfhi(p3) * uu.w;
        }
        *(float2*)&s_ps[(h << 8) + (j << 1)] = make_float2(a0, a1);
        __syncthreads();

        float kt = s_ps[t] + s_ps[256 + t];
        s_v[t] = __fdividef(s_b[t], kt + EPS_DIV);
        __syncthreads();

        // step 2: K_v[n] = sum_m K[n][m] * v[m]    (row access)
        float acc = 0.f;
        #pragma unroll 8
        for (int m = 0; m < 256; m += 4) {
            float4 vv = *(const float4*)&s_v[m];
            unsigned int q0 = sKw[t * 129 + (m >> 1)];
            unsigned int q1 = sKw[t * 129 + (m >> 1) + 1];
            acc += bflo(q0) * vv.x + bfhi(q0) * vv.y
                 + bflo(q1) * vv.z + bfhi(q1) * vv.w;
        }
        s_u[t] = __fdividef(s_a[t], acc + EPS_DIV);
        __syncthreads();
    }

    // ---------- ot_cost[b] = sum_{n,m} u[n] * K[n,m] * v[m] * C[n,m] ----------
    float acc = 0.f;
    #pragma unroll 4
    for (int k = 0; k < 64; k++) {
        int idx4 = k * 256 + t;
        float4 c = ((const float4*)Cb)[idx4];
        int lin = idx4 * 4;
        int n = lin >> 8;
        int m = lin & 255;
        float un = s_u[n];
        float4 vv = *(const float4*)&s_v[m];
        unsigned int q0 = sKw[n * 129 + (m >> 1)];
        unsigned int q1 = sKw[n * 129 + (m >> 1) + 1];
        acc += un * (bflo(q0) * vv.x * c.x + bfhi(q0) * vv.y * c.y
                   + bflo(q1) * vv.z * c.z + bfhi(q1) * vv.w * c.w);
    }
    #pragma unroll
    for (int o = 16; o; o >>= 1) acc += __shfl_xor_sync(0xffffffffu, acc, o);
    __syncthreads();              // s_ps reuse safe after this
    if ((t & 31) == 0) s_ps[t >> 5] = acc;
    __syncthreads();
    if (t == 0) {
        float s = 0.f;
        #pragma unroll
        for (int w = 0; w < 8; w++) s += s_ps[w];
        g_cost[b] = s;
    }
}

__global__ void reduce_kernel(float* __restrict__ out)
{
    __shared__ float sm[8];
    int t = threadIdx.x;
    float s = 0.f;
    #pragma unroll
    for (int i = t; i < B_TOT; i += 256) s += g_cost[i];
    #pragma unroll
    for (int o = 16; o; o >>= 1) s += __shfl_xor_sync(0xffffffffu, s, o);
    if ((t & 31) == 0) sm[t >> 5] = s;
    __syncthreads();
    if (t == 0) {
        float tot = 0.f;
        #pragma unroll
        for (int w = 0; w < 8; w++) tot += sm[w];
        out[0] = tot * (1.0f / B_TOT);
    }
}

extern "C" void kernel_launch(void* const* d_in, const int* in_sizes, int n_in,
                              void* d_out, int out_size)
{
    const float* C  = (const float*)d_in[0];
    const float* mp = (const float*)d_in[1];
    const float* mt = (const float*)d_in[2];
    float* out = (float*)d_out;

    cudaFuncSetAttribute(sinkhorn_kernel,
                         cudaFuncAttributeMaxDynamicSharedMemorySize, SMEM_BYTES);

    sinkhorn_kernel<<<B_TOT, 256, SMEM_BYTES>>>(C, mp, mt);
    reduce_kernel<<<1, 256>>>(out);
}